// round 2
// baseline (speedup 1.0000x reference)
#include <cuda_runtime.h>
#include <math.h>

static constexpr int T    = 32;
static constexpr int IMGW = 512, IMGH = 512, NIMG = 48;   // 16*3 images of 512x512
static constexpr int TILES = (IMGW / T) * (IMGH / T) * NIMG;  // 12288
static constexpr float FEPS = 1e-8f;

// per-(window,block) partial sums; every slot written every launch -> deterministic
__device__ double g_partial[3 * TILES];

template <int K>
__global__ __launch_bounds__(256)
void statloss_kernel(const float* __restrict__ pred,
                     const float* __restrict__ target,
                     int winIdx)
{
    constexpr int R   = K / 2;
    constexpr int H   = T + 4 * R;     // x tile extent (halo 2R)
    constexpr int M   = T + 2 * R;     // mean/xc extent (halo R)
    constexpr int XS  = H + 1;
    constexpr int MS  = M + 1;
    constexpr int NYH = (H + 7) / 8;   // y-iters over H rows (8 thread-rows)
    constexpr int NYM = (M + 7) / 8;   // y-iters over M rows

    __shared__ float sX[H * XS];
    __shared__ float sT1[H * MS];
    __shared__ float sT2[H * MS];
    __shared__ float sMEAN[M * MS];
    __shared__ float sC3[M * MS];
    __shared__ float sC4[M * MS];
    __shared__ double sRed[8];

    const int tx = threadIdx.x;        // 0..31
    const int ty = threadIdx.y;        // 0..7
    const int tid = ty * 32 + tx;

    // normalized 1-D gaussian (separable; outer product is already sum-1)
    float g[K];
    {
        const float sigma = (float)K / 6.0f;
        float s = 0.f;
#pragma unroll
        for (int i = 0; i < K; i++) {
            float c = (float)(i - K / 2);
            g[i] = expf(-c * c / (2.0f * sigma * sigma));
            s += g[i];
        }
#pragma unroll
        for (int i = 0; i < K; i++) g[i] /= s;
    }

    const int gx0 = blockIdx.x * T;
    const int gy0 = blockIdx.y * T;
    const size_t base = (size_t)blockIdx.z * IMGH * IMGW;
    const bool interior = (gx0 >= 2 * R) && (gx0 + T + 2 * R <= IMGW) &&
                          (gy0 >= 2 * R) && (gy0 + T + 2 * R <= IMGH);

    float fmean[2][4], fvar[2][4], fskew[2][4], fkurt[2][4];

    for (int which = 0; which < 2; which++) {
        const float* xin = (which == 0 ? pred : target) + base;

        // ---- load x tile with 2R halo ----
        if (interior) {
            const float* src = xin + (size_t)(gy0 - 2 * R) * IMGW + (gx0 - 2 * R);
#pragma unroll
            for (int q = 0; q < NYH; q++) {
                int j = ty + 8 * q;
                if (j < H) {
                    sX[j * XS + tx] = src[(size_t)j * IMGW + tx];
                    if (tx + 32 < H)
                        sX[j * XS + tx + 32] = src[(size_t)j * IMGW + tx + 32];
                }
            }
        } else {
#pragma unroll
            for (int q = 0; q < NYH; q++) {
                int j = ty + 8 * q;
                if (j < H) {
                    int gy = gy0 - 2 * R + j;
#pragma unroll
                    for (int p = 0; p < 2; p++) {
                        int i = tx + 32 * p;
                        if (i < H) {
                            int gx = gx0 - 2 * R + i;
                            float v = 0.f;
                            if ((unsigned)gy < (unsigned)IMGH && (unsigned)gx < (unsigned)IMGW)
                                v = xin[(size_t)gy * IMGW + gx];
                            sX[j * XS + i] = v;
                        }
                    }
                }
            }
        }
        __syncthreads();

        // ---- P1: horizontal conv of x and x^2  (H rows x M cols) ----
#pragma unroll
        for (int q = 0; q < NYH; q++) {
            int j = ty + 8 * q;
            if (j < H) {
#pragma unroll
                for (int p = 0; p < 2; p++) {
                    int i = tx + 32 * p;
                    if (i < M) {
                        float a = 0.f, b = 0.f;
#pragma unroll
                        for (int d = 0; d < K; d++) {
                            float v = sX[j * XS + i + d];
                            a = fmaf(g[d], v, a);
                            b = fmaf(g[d] * v, v, b);
                        }
                        sT1[j * MS + i] = a;
                        sT2[j * MS + i] = b;
                    }
                }
            }
        }
        __syncthreads();

        // ---- P2: vertical conv -> MEAN (M x M); s2 only at center ----
#pragma unroll
        for (int q = 0; q < NYM; q++) {
            int m = ty + 8 * q;
            if (m < M) {
#pragma unroll
                for (int p = 0; p < 2; p++) {
                    int i = tx + 32 * p;
                    if (i < M) {
                        float a = 0.f;
#pragma unroll
                        for (int d = 0; d < K; d++)
                            a = fmaf(g[d], sT1[(m + d) * MS + i], a);
                        sMEAN[m * MS + i] = a;
                    }
                }
            }
        }
        float s2q[4];
#pragma unroll
        for (int q = 0; q < 4; q++) {
            int yy = ty + 8 * q;
            float b = 0.f;
#pragma unroll
            for (int d = 0; d < K; d++)
                b = fmaf(g[d], sT2[(yy + R + d) * MS + tx + R], b);
            s2q[q] = b;
        }
        __syncthreads();

        // ---- P3: xc^3, xc^4 on the M x M grid (xc==0 outside image) ----
        if (interior) {
#pragma unroll
            for (int q = 0; q < NYM; q++) {
                int m = ty + 8 * q;
                if (m < M) {
#pragma unroll
                    for (int p = 0; p < 2; p++) {
                        int i = tx + 32 * p;
                        if (i < M) {
                            float c = sX[(m + R) * XS + i + R] - sMEAN[m * MS + i];
                            float c3 = c * c * c;
                            sC3[m * MS + i] = c3;
                            sC4[m * MS + i] = c3 * c;
                        }
                    }
                }
            }
        } else {
#pragma unroll
            for (int q = 0; q < NYM; q++) {
                int m = ty + 8 * q;
                if (m < M) {
                    int gy = gy0 - R + m;
#pragma unroll
                    for (int p = 0; p < 2; p++) {
                        int i = tx + 32 * p;
                        if (i < M) {
                            int gx = gx0 - R + i;
                            float c = 0.f;
                            if ((unsigned)gy < (unsigned)IMGH && (unsigned)gx < (unsigned)IMGW)
                                c = sX[(m + R) * XS + i + R] - sMEAN[m * MS + i];
                            float c3 = c * c * c;
                            sC3[m * MS + i] = c3;
                            sC4[m * MS + i] = c3 * c;
                        }
                    }
                }
            }
        }
        float meanq[4];
#pragma unroll
        for (int q = 0; q < 4; q++)
            meanq[q] = sMEAN[(ty + 8 * q + R) * MS + tx + R];
        __syncthreads();

        // ---- P4: horizontal conv of xc^3/xc^4 (M rows x T cols) ----
#pragma unroll
        for (int q = 0; q < NYM; q++) {
            int m = ty + 8 * q;
            if (m < M) {
                float a = 0.f, b = 0.f;
#pragma unroll
                for (int d = 0; d < K; d++) {
                    a = fmaf(g[d], sC3[m * MS + tx + d], a);
                    b = fmaf(g[d], sC4[m * MS + tx + d], b);
                }
                sT1[m * MS + tx] = a;
                sT2[m * MS + tx] = b;
            }
        }
        __syncthreads();

        // ---- P5: vertical conv -> m3, m4; final features ----
#pragma unroll
        for (int q = 0; q < 4; q++) {
            int yy = ty + 8 * q;
            float m3 = 0.f, m4 = 0.f;
#pragma unroll
            for (int d = 0; d < K; d++) {
                m3 = fmaf(g[d], sT1[(yy + d) * MS + tx], m3);
                m4 = fmaf(g[d], sT2[(yy + d) * MS + tx], m4);
            }
            float mean = meanq[q];
            float var  = fmaxf(s2q[q] - mean * mean, FEPS);
            float sd   = sqrtf(var);
            fmean[which][q] = mean;
            fvar[which][q]  = var;
            fskew[which][q] = m3 / (sd * sd * sd + FEPS);
            fkurt[which][q] = m4 / (var * var + FEPS);
        }
        __syncthreads();   // before smem reuse by next input
    }

    // ---- per-thread loss, block reduce in double ----
    double acc = 0.0;
#pragma unroll
    for (int q = 0; q < 4; q++) {
        acc += 1.0   * (double)fabsf(fmean[0][q] - fmean[1][q]);
        acc += 1.0   * (double)fabsf(fvar[0][q]  - fvar[1][q]);
        acc += 0.5   * (double)fabsf(fskew[0][q] - fskew[1][q]);
        acc += 0.001 * (double)fabsf(fkurt[0][q] - fkurt[1][q]);
    }
#pragma unroll
    for (int o = 16; o > 0; o >>= 1)
        acc += __shfl_down_sync(0xffffffffu, acc, o);
    if (tx == 0) sRed[ty] = acc;
    __syncthreads();
    if (tid < 8) {
        double a = sRed[tid];
#pragma unroll
        for (int o = 4; o > 0; o >>= 1)
            a += __shfl_down_sync(0xffu, a, o);
        if (tid == 0) {
            int blin = (blockIdx.z * gridDim.y + blockIdx.y) * gridDim.x + blockIdx.x;
            g_partial[winIdx * TILES + blin] = a;
        }
    }
}

__global__ __launch_bounds__(1024)
void finalize_kernel(float* __restrict__ out)
{
    __shared__ double sRed[32];
    double a = 0.0;
#pragma unroll 4
    for (int i = threadIdx.x; i < 3 * TILES; i += 1024) a += g_partial[i];
#pragma unroll
    for (int o = 16; o > 0; o >>= 1)
        a += __shfl_down_sync(0xffffffffu, a, o);
    if ((threadIdx.x & 31) == 0) sRed[threadIdx.x >> 5] = a;
    __syncthreads();
    if (threadIdx.x < 32) {
        double v = sRed[threadIdx.x];
#pragma unroll
        for (int o = 16; o > 0; o >>= 1)
            v += __shfl_down_sync(0xffffffffu, v, o);
        if (threadIdx.x == 0) {
            const double npix = (double)16 * 3 * 512 * 512;
            out[0] = (float)(v / (npix * 12.0));
        }
    }
}

extern "C" void kernel_launch(void* const* d_in, const int* in_sizes, int n_in,
                              void* d_out, int out_size)
{
    const float* pred   = (const float*)d_in[0];
    const float* target = (const float*)d_in[1];

    dim3 grid(IMGW / T, IMGH / T, NIMG);   // 16 x 16 x 48 tiles
    dim3 blk(32, 8);
    statloss_kernel<3><<<grid, blk>>>(pred, target, 0);
    statloss_kernel<5><<<grid, blk>>>(pred, target, 1);
    statloss_kernel<7><<<grid, blk>>>(pred, target, 2);
    finalize_kernel<<<1, 1024>>>((float*)d_out);
}